// round 2
// baseline (speedup 1.0000x reference)
#include <cuda_runtime.h>

#define N_NODES 100000
#define N_EDGES 1600000
#define FIN 128
#define HF 128            // H*F = 8*16
#define NHEAD 8
#define C2 40
#define NEG 0.2f
#define SCAN_NBLK 98      // ceil(100000/1024)

// ---------------- scratch (static device globals; no allocation) ----------------
__device__ float g_h1[N_NODES * HF];     // layer-1 projected features
__device__ float g_as1[N_NODES * NHEAD]; // alpha_src per node/head (layer 1)
__device__ float g_ad1[N_NODES * NHEAD];
__device__ float g_h2[N_NODES * HF];     // elu(agg1 + b1) = layer-2 input
__device__ float g_hp2[N_NODES * C2];    // layer-2 projected features
__device__ float g_as2[N_NODES];
__device__ float g_ad2[N_NODES];
__device__ int   g_deg[N_NODES];
__device__ int   g_rowptr[N_NODES + 1];
__device__ int   g_cursor[N_NODES];
__device__ int   g_csr[N_EDGES];         // src node per incoming edge, grouped by dst
__device__ int   g_bsum[128];
__device__ int   g_boff[128];

// ---------------- CSR build ----------------
__global__ void zero_deg_kernel() {
    int i = blockIdx.x * blockDim.x + threadIdx.x;
    if (i < N_NODES) g_deg[i] = 0;
}

__global__ void count_deg_kernel(const int* __restrict__ edst) {
    int i = blockIdx.x * blockDim.x + threadIdx.x;
    if (i < N_EDGES) atomicAdd(&g_deg[edst[i]], 1);
}

__global__ void scan_a_kernel() {
    __shared__ int sh[1024];
    int t = threadIdx.x;
    int i = blockIdx.x * 1024 + t;
    int v = (i < N_NODES) ? g_deg[i] : 0;
    sh[t] = v;
    __syncthreads();
    for (int off = 1; off < 1024; off <<= 1) {
        int add = (t >= off) ? sh[t - off] : 0;
        __syncthreads();
        sh[t] += add;
        __syncthreads();
    }
    int incl = sh[t];
    if (i < N_NODES) g_rowptr[i] = incl - v;       // exclusive, pre-block-offset
    if (t == 1023) g_bsum[blockIdx.x] = incl;
}

__global__ void scan_b_kernel() {
    __shared__ int sh[128];
    int t = threadIdx.x;
    int v = (t < SCAN_NBLK) ? g_bsum[t] : 0;
    sh[t] = v;
    __syncthreads();
    for (int off = 1; off < 128; off <<= 1) {
        int add = (t >= off) ? sh[t - off] : 0;
        __syncthreads();
        sh[t] += add;
        __syncthreads();
    }
    int incl = sh[t];
    if (t < SCAN_NBLK) g_boff[t] = incl - v;
    if (t == 127) g_rowptr[N_NODES] = incl;        // total = E
}

__global__ void scan_c_kernel() {
    int i = blockIdx.x * blockDim.x + threadIdx.x;
    if (i < N_NODES) {
        int rp = g_rowptr[i] + g_boff[i >> 10];
        g_rowptr[i] = rp;
        g_cursor[i] = rp;
    }
}

__global__ void scatter_kernel(const int* __restrict__ esrc,
                               const int* __restrict__ edst) {
    int i = blockIdx.x * blockDim.x + threadIdx.x;
    if (i < N_EDGES) {
        int d = edst[i];
        int s = esrc[i];
        int p = atomicAdd(&g_cursor[d], 1);
        g_csr[p] = s;
    }
}

// ---------------- GEMM1: h1 = x @ W1 (+ fused alpha_src/alpha_dst) ----------------
// block = 256 threads = tx(32 colgroups of 4) x ty(8 node-subgroups of 8) -> 64 nodes/block
__global__ void gemm1_kernel(const float* __restrict__ x, const float* __restrict__ W,
                             const float* __restrict__ a_s, const float* __restrict__ a_d) {
    __shared__ float xs[64][FIN];
    int node0 = blockIdx.x * 64;
    int tid = threadIdx.x;
    int tx = tid & 31, ty = tid >> 5;

    // cooperative float4 load of 64 x-rows
    for (int i = tid; i < 64 * 32; i += 256) {
        int r = i >> 5, c = i & 31;
        int row = node0 + r;
        float4 v = make_float4(0.f, 0.f, 0.f, 0.f);
        if (row < N_NODES) v = reinterpret_cast<const float4*>(x + (size_t)row * FIN)[c];
        *reinterpret_cast<float4*>(&xs[r][c * 4]) = v;
    }
    __syncthreads();

    float4 acc[8];
#pragma unroll
    for (int r = 0; r < 8; r++) acc[r] = make_float4(0.f, 0.f, 0.f, 0.f);

    const float4* W4 = reinterpret_cast<const float4*>(W);
    int rbase = ty * 8;
#pragma unroll 4
    for (int k = 0; k < FIN; k++) {
        float4 w = __ldg(&W4[k * 32 + tx]);
#pragma unroll
        for (int r = 0; r < 8; r++) {
            float xv = xs[rbase + r][k];
            acc[r].x += xv * w.x; acc[r].y += xv * w.y;
            acc[r].z += xv * w.z; acc[r].w += xv * w.w;
        }
    }

    float4 av = __ldg(&reinterpret_cast<const float4*>(a_s)[tx]);
    float4 dv = __ldg(&reinterpret_cast<const float4*>(a_d)[tx]);
#pragma unroll
    for (int r = 0; r < 8; r++) {
        int node = node0 + rbase + r;
        if (node >= N_NODES) continue;   // warp-uniform
        reinterpret_cast<float4*>(g_h1 + (size_t)node * HF)[tx] = acc[r];
        float ps = acc[r].x * av.x + acc[r].y * av.y + acc[r].z * av.z + acc[r].w * av.w;
        float pd = acc[r].x * dv.x + acc[r].y * dv.y + acc[r].z * dv.z + acc[r].w * dv.w;
        // reduce within each 4-lane head group (16 feats / 4 per lane)
        ps += __shfl_xor_sync(0xffffffffu, ps, 1);
        ps += __shfl_xor_sync(0xffffffffu, ps, 2);
        pd += __shfl_xor_sync(0xffffffffu, pd, 1);
        pd += __shfl_xor_sync(0xffffffffu, pd, 2);
        if ((tx & 3) == 0) {
            g_as1[node * NHEAD + (tx >> 2)] = ps;
            g_ad1[node * NHEAD + (tx >> 2)] = pd;
        }
    }
}

// ---------------- Aggregation layer 1 (softmax + gather, fused bias+ELU) ----------------
// one warp per dst node; lane owns 4 features (head = lane/4)
__global__ void agg1_kernel(const float* __restrict__ b1) {
    int warp = threadIdx.x >> 5, lane = threadIdx.x & 31;
    int n = blockIdx.x * 8 + warp;
    if (n >= N_NODES) return;
    int h = lane >> 2;
    float ad = g_ad1[n * NHEAD + h];
    int beg = g_rowptr[n], end = g_rowptr[n + 1];
    float4 acc = make_float4(0.f, 0.f, 0.f, 0.f);
    float denom = 0.f;
    for (int i = beg; i < end; i++) {
        int s = g_csr[i];                                  // warp-broadcast
        float e = g_as1[s * NHEAD + h] + ad;
        e = fmaxf(e, NEG * e);                             // leaky_relu(0.2)
        float w = __expf(e);
        denom += w;
        float4 hv = *reinterpret_cast<const float4*>(g_h1 + (size_t)s * HF + lane * 4);
        acc.x += w * hv.x; acc.y += w * hv.y;
        acc.z += w * hv.z; acc.w += w * hv.w;
    }
    float r = 1.0f / fmaxf(denom, 1e-16f);
    float4 bv = *reinterpret_cast<const float4*>(b1 + lane * 4);
    float4 o;
    o.x = acc.x * r + bv.x; o.y = acc.y * r + bv.y;
    o.z = acc.z * r + bv.z; o.w = acc.w * r + bv.w;
    // ELU
    o.x = o.x > 0.f ? o.x : __expf(o.x) - 1.f;
    o.y = o.y > 0.f ? o.y : __expf(o.y) - 1.f;
    o.z = o.z > 0.f ? o.z : __expf(o.z) - 1.f;
    o.w = o.w > 0.f ? o.w : __expf(o.w) - 1.f;
    *reinterpret_cast<float4*>(g_h2 + (size_t)n * HF + lane * 4) = o;
}

// ---------------- GEMM2: hp2 = h2 @ W2 (+ fused alpha2) ----------------
// one warp per node; lane owns col lane (and col 32+lane for lane<8)
__global__ void gemm2_kernel(const float* __restrict__ W2,
                             const float* __restrict__ a_s, const float* __restrict__ a_d) {
    __shared__ float xs[8][FIN];
    int warp = threadIdx.x >> 5, lane = threadIdx.x & 31;
    int node = blockIdx.x * 8 + warp;
    if (node >= N_NODES) return;
    float4 xv4 = reinterpret_cast<const float4*>(g_h2 + (size_t)node * FIN)[lane];
    *reinterpret_cast<float4*>(&xs[warp][lane * 4]) = xv4;
    __syncwarp();
    float acc0 = 0.f, acc1 = 0.f;
#pragma unroll 4
    for (int k = 0; k < FIN; k++) {
        float xv = xs[warp][k];
        acc0 += xv * __ldg(&W2[k * C2 + lane]);
        if (lane < 8) acc1 += xv * __ldg(&W2[k * C2 + 32 + lane]);
    }
    float ps = acc0 * __ldg(&a_s[lane]);
    float pd = acc0 * __ldg(&a_d[lane]);
    if (lane < 8) {
        ps += acc1 * __ldg(&a_s[32 + lane]);
        pd += acc1 * __ldg(&a_d[32 + lane]);
    }
#pragma unroll
    for (int off = 16; off; off >>= 1) {
        ps += __shfl_xor_sync(0xffffffffu, ps, off);
        pd += __shfl_xor_sync(0xffffffffu, pd, off);
    }
    g_hp2[(size_t)node * C2 + lane] = acc0;
    if (lane < 8) g_hp2[(size_t)node * C2 + 32 + lane] = acc1;
    if (lane == 0) { g_as2[node] = ps; g_ad2[node] = pd; }
}

// ---------------- Aggregation layer 2 ----------------
__global__ void agg2_kernel(const float* __restrict__ b2, float* __restrict__ out) {
    int warp = threadIdx.x >> 5, lane = threadIdx.x & 31;
    int n = blockIdx.x * 8 + warp;
    if (n >= N_NODES) return;
    float ad = g_ad2[n];
    int beg = g_rowptr[n], end = g_rowptr[n + 1];
    float acc0 = 0.f, acc1 = 0.f, denom = 0.f;
    for (int i = beg; i < end; i++) {
        int s = g_csr[i];
        float e = g_as2[s] + ad;
        e = fmaxf(e, NEG * e);
        float w = __expf(e);
        denom += w;
        acc0 += w * g_hp2[(size_t)s * C2 + lane];
        if (lane < 8) acc1 += w * g_hp2[(size_t)s * C2 + 32 + lane];
    }
    float r = 1.0f / fmaxf(denom, 1e-16f);
    out[(size_t)n * C2 + lane] = acc0 * r + __ldg(&b2[lane]);
    if (lane < 8) out[(size_t)n * C2 + 32 + lane] = acc1 * r + __ldg(&b2[32 + lane]);
}

// ---------------- launch ----------------
extern "C" void kernel_launch(void* const* d_in, const int* in_sizes, int n_in,
                              void* d_out, int out_size) {
    const float* x    = (const float*)d_in[0];
    const int*   esrc = (const int*)d_in[1];
    const int*   edst = (const int*)d_in[2];
    const float* W1   = (const float*)d_in[3];
    const float* as1  = (const float*)d_in[4];
    const float* ad1  = (const float*)d_in[5];
    const float* b1   = (const float*)d_in[6];
    const float* W2   = (const float*)d_in[7];
    const float* as2  = (const float*)d_in[8];
    const float* ad2  = (const float*)d_in[9];
    const float* b2   = (const float*)d_in[10];
    float*       out  = (float*)d_out;

    zero_deg_kernel<<<(N_NODES + 255) / 256, 256>>>();
    count_deg_kernel<<<(N_EDGES + 255) / 256, 256>>>(edst);
    scan_a_kernel<<<SCAN_NBLK, 1024>>>();
    scan_b_kernel<<<1, 128>>>();
    scan_c_kernel<<<(N_NODES + 255) / 256, 256>>>();
    scatter_kernel<<<(N_EDGES + 255) / 256, 256>>>(esrc, edst);

    gemm1_kernel<<<(N_NODES + 63) / 64, 256>>>(x, W1, as1, ad1);
    agg1_kernel<<<(N_NODES + 7) / 8, 256>>>(b1);
    gemm2_kernel<<<(N_NODES + 7) / 8, 256>>>(W2, as2, ad2);
    agg2_kernel<<<(N_NODES + 7) / 8, 256>>>(b2, out);
}

// round 3
// speedup vs baseline: 1.0135x; 1.0135x over previous
#include <cuda_runtime.h>
#include <cstdint>

#define N_NODES 100000
#define N_EDGES 1600000
#define FIN 128
#define HF 128            // H*F = 8*16
#define NHEAD 8
#define C2 40
#define HP2S 48           // padded stride for hp2 (sector-aligned 192B)
#define NEG 0.2f
#define SCAN_NBLK 98      // ceil(100000/1024)
#define SSTRIDE 136       // smem stride (floats) for gemm1 tiles: conflict-free frag loads

// ---------------- scratch (static device globals; no allocation) ----------------
__device__ float g_h1[N_NODES * HF];       // layer-1 projected features
__device__ float g_as1[N_NODES * NHEAD];
__device__ float g_ad1[N_NODES * NHEAD];
__device__ float g_h2[N_NODES * HF];       // elu(agg1 + b1)
__device__ float g_hp2[N_NODES * HP2S];    // layer-2 projected (padded stride)
__device__ float g_as2[N_NODES];
__device__ float g_ad2[N_NODES];
__device__ int   g_deg[N_NODES];
__device__ int   g_rowptr[N_NODES + 1];
__device__ int   g_cursor[N_NODES];
__device__ int   g_csr[N_EDGES];
__device__ int   g_bsum[128];
__device__ int   g_boff[128];

// ---------------- CSR build ----------------
__global__ void count_deg_kernel(const int* __restrict__ edst) {
    int i = blockIdx.x * blockDim.x + threadIdx.x;
    if (i < N_EDGES) atomicAdd(&g_deg[edst[i]], 1);
}

__global__ void scan_a_kernel() {
    __shared__ int sh[1024];
    int t = threadIdx.x;
    int i = blockIdx.x * 1024 + t;
    int v = (i < N_NODES) ? g_deg[i] : 0;
    sh[t] = v;
    __syncthreads();
    for (int off = 1; off < 1024; off <<= 1) {
        int add = (t >= off) ? sh[t - off] : 0;
        __syncthreads();
        sh[t] += add;
        __syncthreads();
    }
    int incl = sh[t];
    if (i < N_NODES) g_rowptr[i] = incl - v;
    if (t == 1023) g_bsum[blockIdx.x] = incl;
}

__global__ void scan_b_kernel() {
    __shared__ int sh[128];
    int t = threadIdx.x;
    int v = (t < SCAN_NBLK) ? g_bsum[t] : 0;
    sh[t] = v;
    __syncthreads();
    for (int off = 1; off < 128; off <<= 1) {
        int add = (t >= off) ? sh[t - off] : 0;
        __syncthreads();
        sh[t] += add;
        __syncthreads();
    }
    int incl = sh[t];
    if (t < SCAN_NBLK) g_boff[t] = incl - v;
    if (t == 127) g_rowptr[N_NODES] = incl;
}

__global__ void scan_c_kernel() {
    int i = blockIdx.x * blockDim.x + threadIdx.x;
    if (i < N_NODES) {
        int rp = g_rowptr[i] + g_boff[i >> 10];
        g_rowptr[i] = rp;
        g_cursor[i] = rp;
    }
}

__global__ void scatter_kernel(const int* __restrict__ esrc,
                               const int* __restrict__ edst) {
    int i = blockIdx.x * blockDim.x + threadIdx.x;
    if (i < N_EDGES) {
        int p = atomicAdd(&g_cursor[edst[i]], 1);
        g_csr[p] = esrc[i];
    }
}

// ---------------- GEMM1 (tf32 tensor cores): h1 = x @ W1 ----------------
// block = 256 thr (8 warps). Tile M=128 nodes, N=128, K=128.
// As[row][k] and Ws[k][n] staged in dynamic smem with stride 136 (bank-conflict-free
// fragment loads), values pre-converted to tf32 bits at load time.
__global__ void gemm1_tf32_kernel(const float* __restrict__ x, const float* __restrict__ W) {
    extern __shared__ float smem[];
    float* As = smem;                    // 128 x SSTRIDE
    float* Ws = smem + 128 * SSTRIDE;    // 128 x SSTRIDE
    int node0 = blockIdx.x * 128;
    int tid = threadIdx.x;

    // load + convert A tile (zero-fill OOB rows)
    for (int i = tid; i < 128 * 32; i += 256) {
        int r = i >> 5, c4 = i & 31;
        int row = node0 + r;
        float4 v = make_float4(0.f, 0.f, 0.f, 0.f);
        if (row < N_NODES) v = reinterpret_cast<const float4*>(x + (size_t)row * FIN)[c4];
        uint32_t u0, u1, u2, u3;
        asm("cvt.rna.tf32.f32 %0, %1;" : "=r"(u0) : "f"(v.x));
        asm("cvt.rna.tf32.f32 %0, %1;" : "=r"(u1) : "f"(v.y));
        asm("cvt.rna.tf32.f32 %0, %1;" : "=r"(u2) : "f"(v.z));
        asm("cvt.rna.tf32.f32 %0, %1;" : "=r"(u3) : "f"(v.w));
        *reinterpret_cast<uint4*>(&As[r * SSTRIDE + c4 * 4]) = make_uint4(u0, u1, u2, u3);
    }
    // load + convert W tile
    for (int i = tid; i < 128 * 32; i += 256) {
        int k = i >> 5, c4 = i & 31;
        float4 v = reinterpret_cast<const float4*>(W + k * HF)[c4];
        uint32_t u0, u1, u2, u3;
        asm("cvt.rna.tf32.f32 %0, %1;" : "=r"(u0) : "f"(v.x));
        asm("cvt.rna.tf32.f32 %0, %1;" : "=r"(u1) : "f"(v.y));
        asm("cvt.rna.tf32.f32 %0, %1;" : "=r"(u2) : "f"(v.z));
        asm("cvt.rna.tf32.f32 %0, %1;" : "=r"(u3) : "f"(v.w));
        *reinterpret_cast<uint4*>(&Ws[k * SSTRIDE + c4 * 4]) = make_uint4(u0, u1, u2, u3);
    }
    __syncthreads();

    int warp = tid >> 5, lane = tid & 31;
    int qr = lane >> 2;          // 0..7
    int qc = lane & 3;           // 0..3
    int arow = warp * 16 + qr;   // A fragment row (within tile)

    float c[16][4];
#pragma unroll
    for (int t = 0; t < 16; t++) { c[t][0] = c[t][1] = c[t][2] = c[t][3] = 0.f; }

    const uint32_t* Asu = reinterpret_cast<const uint32_t*>(As);
    const uint32_t* Wsu = reinterpret_cast<const uint32_t*>(Ws);

#pragma unroll
    for (int ks = 0; ks < 16; ks++) {
        int k0 = ks * 8;
        uint32_t a0 = Asu[arow * SSTRIDE + k0 + qc];
        uint32_t a1 = Asu[(arow + 8) * SSTRIDE + k0 + qc];
        uint32_t a2 = Asu[arow * SSTRIDE + k0 + 4 + qc];
        uint32_t a3 = Asu[(arow + 8) * SSTRIDE + k0 + 4 + qc];
#pragma unroll
        for (int nt = 0; nt < 16; nt++) {
            uint32_t b0 = Wsu[(k0 + qc) * SSTRIDE + nt * 8 + qr];
            uint32_t b1 = Wsu[(k0 + 4 + qc) * SSTRIDE + nt * 8 + qr];
            asm("mma.sync.aligned.m16n8k8.row.col.f32.tf32.tf32.f32 "
                "{%0,%1,%2,%3}, {%4,%5,%6,%7}, {%8,%9}, {%0,%1,%2,%3};"
                : "+f"(c[nt][0]), "+f"(c[nt][1]), "+f"(c[nt][2]), "+f"(c[nt][3])
                : "r"(a0), "r"(a1), "r"(a2), "r"(a3), "r"(b0), "r"(b1));
        }
    }

    int r0 = node0 + arow;
    int r1 = r0 + 8;
#pragma unroll
    for (int nt = 0; nt < 16; nt++) {
        int col = nt * 8 + qc * 2;
        if (r0 < N_NODES)
            *reinterpret_cast<float2*>(&g_h1[(size_t)r0 * HF + col]) = make_float2(c[nt][0], c[nt][1]);
        if (r1 < N_NODES)
            *reinterpret_cast<float2*>(&g_h1[(size_t)r1 * HF + col]) = make_float2(c[nt][2], c[nt][3]);
    }
}

// ---------------- alpha1: per-node attention coefficients from h1 ----------------
__global__ void alpha1_kernel(const float* __restrict__ a_s, const float* __restrict__ a_d) {
    int warp = threadIdx.x >> 5, lane = threadIdx.x & 31;
    int n = blockIdx.x * 8 + warp;
    if (n >= N_NODES) return;
    float4 h = *reinterpret_cast<const float4*>(&g_h1[(size_t)n * HF + lane * 4]);
    float4 av = __ldg(&reinterpret_cast<const float4*>(a_s)[lane]);
    float4 dv = __ldg(&reinterpret_cast<const float4*>(a_d)[lane]);
    float ps = h.x * av.x + h.y * av.y + h.z * av.z + h.w * av.w;
    float pd = h.x * dv.x + h.y * dv.y + h.z * dv.z + h.w * dv.w;
    ps += __shfl_xor_sync(0xffffffffu, ps, 1);
    ps += __shfl_xor_sync(0xffffffffu, ps, 2);
    pd += __shfl_xor_sync(0xffffffffu, pd, 1);
    pd += __shfl_xor_sync(0xffffffffu, pd, 2);
    if ((lane & 3) == 0) {
        g_as1[n * NHEAD + (lane >> 2)] = ps;
        g_ad1[n * NHEAD + (lane >> 2)] = pd;
    }
}

// ---------------- Aggregation layer 1 (softmax + gather, fused bias+ELU) ----------------
__global__ void agg1_kernel(const float* __restrict__ b1) {
    int warp = threadIdx.x >> 5, lane = threadIdx.x & 31;
    int n = blockIdx.x * 8 + warp;
    if (n >= N_NODES) return;
    int h = lane >> 2;
    float ad = __ldg(&g_ad1[n * NHEAD + h]);
    int beg = __ldg(&g_rowptr[n]), end = __ldg(&g_rowptr[n + 1]);
    float4 acc = make_float4(0.f, 0.f, 0.f, 0.f);
    float denom = 0.f;
    int s_next = (beg < end) ? __ldg(&g_csr[beg]) : 0;
#pragma unroll 2
    for (int i = beg; i < end; i++) {
        int s = s_next;
        if (i + 1 < end) s_next = __ldg(&g_csr[i + 1]);
        float e = __ldg(&g_as1[s * NHEAD + h]) + ad;
        e = fmaxf(e, NEG * e);
        float w = __expf(e);
        denom += w;
        float4 hv = *reinterpret_cast<const float4*>(&g_h1[(size_t)s * HF + lane * 4]);
        acc.x += w * hv.x; acc.y += w * hv.y;
        acc.z += w * hv.z; acc.w += w * hv.w;
    }
    float r = 1.0f / fmaxf(denom, 1e-16f);
    float4 bv = __ldg(&reinterpret_cast<const float4*>(b1)[lane]);
    float4 o;
    o.x = acc.x * r + bv.x; o.y = acc.y * r + bv.y;
    o.z = acc.z * r + bv.z; o.w = acc.w * r + bv.w;
    o.x = o.x > 0.f ? o.x : __expf(o.x) - 1.f;
    o.y = o.y > 0.f ? o.y : __expf(o.y) - 1.f;
    o.z = o.z > 0.f ? o.z : __expf(o.z) - 1.f;
    o.w = o.w > 0.f ? o.w : __expf(o.w) - 1.f;
    *reinterpret_cast<float4*>(&g_h2[(size_t)n * HF + lane * 4]) = o;
}

// ---------------- GEMM2: hp2 = h2 @ W2 (+ fused alpha2), W2 staged in smem ----------------
__global__ void gemm2_kernel(const float* __restrict__ W2,
                             const float* __restrict__ a_s, const float* __restrict__ a_d) {
    __shared__ float ws[FIN * C2];   // 20 KB
    __shared__ float xs[8][FIN];
    int tid = threadIdx.x;
    for (int i = tid; i < FIN * C2; i += 256) ws[i] = W2[i];
    int warp = tid >> 5, lane = tid & 31;
    int node = blockIdx.x * 8 + warp;
    bool live = (node < N_NODES);
    if (live) {
        float4 xv4 = reinterpret_cast<const float4*>(g_h2 + (size_t)node * FIN)[lane];
        *reinterpret_cast<float4*>(&xs[warp][lane * 4]) = xv4;
    }
    __syncthreads();
    if (!live) return;
    float acc0 = 0.f, acc1 = 0.f;
#pragma unroll 4
    for (int k = 0; k < FIN; k++) {
        float xv = xs[warp][k];
        acc0 += xv * ws[k * C2 + lane];
        if (lane < 8) acc1 += xv * ws[k * C2 + 32 + lane];
    }
    float ps = acc0 * __ldg(&a_s[lane]);
    float pd = acc0 * __ldg(&a_d[lane]);
    if (lane < 8) {
        ps += acc1 * __ldg(&a_s[32 + lane]);
        pd += acc1 * __ldg(&a_d[32 + lane]);
    }
#pragma unroll
    for (int off = 16; off; off >>= 1) {
        ps += __shfl_xor_sync(0xffffffffu, ps, off);
        pd += __shfl_xor_sync(0xffffffffu, pd, off);
    }
    g_hp2[(size_t)node * HP2S + lane] = acc0;
    if (lane < 8) g_hp2[(size_t)node * HP2S + 32 + lane] = acc1;
    if (lane == 0) { g_as2[node] = ps; g_ad2[node] = pd; }
}

// ---------------- Aggregation layer 2 ----------------
__global__ void agg2_kernel(const float* __restrict__ b2, float* __restrict__ out) {
    int warp = threadIdx.x >> 5, lane = threadIdx.x & 31;
    int n = blockIdx.x * 8 + warp;
    if (n >= N_NODES) return;
    float ad = __ldg(&g_ad2[n]);
    int beg = __ldg(&g_rowptr[n]), end = __ldg(&g_rowptr[n + 1]);
    float acc0 = 0.f, acc1 = 0.f, denom = 0.f;
    int s_next = (beg < end) ? __ldg(&g_csr[beg]) : 0;
#pragma unroll 2
    for (int i = beg; i < end; i++) {
        int s = s_next;
        if (i + 1 < end) s_next = __ldg(&g_csr[i + 1]);
        float e = __ldg(&g_as2[s]) + ad;
        e = fmaxf(e, NEG * e);
        float w = __expf(e);
        denom += w;
        acc0 += w * __ldg(&g_hp2[(size_t)s * HP2S + lane]);
        if (lane < 8) acc1 += w * __ldg(&g_hp2[(size_t)s * HP2S + 32 + lane]);
    }
    float r = 1.0f / fmaxf(denom, 1e-16f);
    out[(size_t)n * C2 + lane] = acc0 * r + __ldg(&b2[lane]);
    if (lane < 8) out[(size_t)n * C2 + 32 + lane] = acc1 * r + __ldg(&b2[32 + lane]);
}

// ---------------- launch ----------------
extern "C" void kernel_launch(void* const* d_in, const int* in_sizes, int n_in,
                              void* d_out, int out_size) {
    const float* x    = (const float*)d_in[0];
    const int*   esrc = (const int*)d_in[1];
    const int*   edst = (const int*)d_in[2];
    const float* W1   = (const float*)d_in[3];
    const float* as1  = (const float*)d_in[4];
    const float* ad1  = (const float*)d_in[5];
    const float* b1   = (const float*)d_in[6];
    const float* W2   = (const float*)d_in[7];
    const float* as2  = (const float*)d_in[8];
    const float* ad2  = (const float*)d_in[9];
    const float* b2   = (const float*)d_in[10];
    float*       out  = (float*)d_out;

    void* degptr = nullptr;
    cudaGetSymbolAddress(&degptr, g_deg);
    cudaMemsetAsync(degptr, 0, N_NODES * sizeof(int));

    count_deg_kernel<<<(N_EDGES + 255) / 256, 256>>>(edst);
    scan_a_kernel<<<SCAN_NBLK, 1024>>>();
    scan_b_kernel<<<1, 128>>>();
    scan_c_kernel<<<(N_NODES + 255) / 256, 256>>>();
    scatter_kernel<<<(N_EDGES + 255) / 256, 256>>>(esrc, edst);

    int smem_bytes = 2 * 128 * SSTRIDE * sizeof(float);  // 139264
    cudaFuncSetAttribute(gemm1_tf32_kernel, cudaFuncAttributeMaxDynamicSharedMemorySize, smem_bytes);
    gemm1_tf32_kernel<<<(N_NODES + 127) / 128, 256, smem_bytes>>>(x, W1);
    alpha1_kernel<<<(N_NODES + 7) / 8, 256>>>(as1, ad1);
    agg1_kernel<<<(N_NODES + 7) / 8, 256>>>(b1);
    gemm2_kernel<<<(N_NODES + 7) / 8, 256>>>(W2, as2, ad2);
    agg2_kernel<<<(N_NODES + 7) / 8, 256>>>(b2, out);
}

// round 4
// speedup vs baseline: 1.3772x; 1.3588x over previous
#include <cuda_runtime.h>
#include <cuda_fp16.h>
#include <cstdint>

#define N_NODES 100000
#define N_EDGES 1600000
#define FIN 128
#define HF 128            // H*F = 8*16
#define NHEAD 8
#define C2 40
#define HP2S 48           // padded stride for hp2
#define NEG 0.2f
#define SCAN_NBLK 98
#define SSTRIDE 136       // smem stride (floats), conflict-free frag loads

// ---------------- scratch ----------------
__device__ __half g_h1h[N_NODES * HF];     // layer-1 features (fp16 for gather)
__device__ float  g_as1[N_NODES * NHEAD];
__device__ float  g_ad1[N_NODES * NHEAD];
__device__ float  g_h2[N_NODES * HF];      // elu(agg1 + b1)
__device__ float  g_hp2[N_NODES * HP2S];
__device__ float  g_as2[N_NODES];
__device__ float  g_ad2[N_NODES];
__device__ int    g_deg[N_NODES];
__device__ int    g_rowptr[N_NODES + 1];
__device__ int    g_cursor[N_NODES];
__device__ int    g_csr[N_EDGES];
__device__ int    g_bsum[128];
__device__ int    g_boff[128];

// ---------------- CSR build ----------------
__global__ void count_deg_kernel(const int* __restrict__ edst) {
    int i = blockIdx.x * blockDim.x + threadIdx.x;
    if (i < N_EDGES) atomicAdd(&g_deg[edst[i]], 1);
}

__global__ void scan_a_kernel() {
    __shared__ int sh[1024];
    int t = threadIdx.x;
    int i = blockIdx.x * 1024 + t;
    int v = (i < N_NODES) ? g_deg[i] : 0;
    sh[t] = v;
    __syncthreads();
    for (int off = 1; off < 1024; off <<= 1) {
        int add = (t >= off) ? sh[t - off] : 0;
        __syncthreads();
        sh[t] += add;
        __syncthreads();
    }
    int incl = sh[t];
    if (i < N_NODES) g_rowptr[i] = incl - v;
    if (t == 1023) g_bsum[blockIdx.x] = incl;
}

__global__ void scan_b_kernel() {
    __shared__ int sh[128];
    int t = threadIdx.x;
    int v = (t < SCAN_NBLK) ? g_bsum[t] : 0;
    sh[t] = v;
    __syncthreads();
    for (int off = 1; off < 128; off <<= 1) {
        int add = (t >= off) ? sh[t - off] : 0;
        __syncthreads();
        sh[t] += add;
        __syncthreads();
    }
    int incl = sh[t];
    if (t < SCAN_NBLK) g_boff[t] = incl - v;
    if (t == 127) g_rowptr[N_NODES] = incl;
}

__global__ void scan_c_kernel() {
    int i = blockIdx.x * blockDim.x + threadIdx.x;
    if (i < N_NODES) {
        int rp = g_rowptr[i] + g_boff[i >> 10];
        g_rowptr[i] = rp;
        g_cursor[i] = rp;
    }
}

__global__ void scatter_kernel(const int* __restrict__ esrc,
                               const int* __restrict__ edst) {
    int i = blockIdx.x * blockDim.x + threadIdx.x;
    if (i < N_EDGES) {
        int p = atomicAdd(&g_cursor[edst[i]], 1);
        g_csr[p] = esrc[i];
    }
}

// ---------------- GEMM1 (tf32 mma) + fused alpha1 epilogue, h1 -> fp16 ----------------
__global__ __launch_bounds__(256) void gemm1_tf32_kernel(
        const float* __restrict__ x, const float* __restrict__ W,
        const float* __restrict__ a_s, const float* __restrict__ a_d) {
    extern __shared__ float smem[];
    float* As = smem;                        // 128 x SSTRIDE
    float* Ws = smem + 128 * SSTRIDE;        // 128 x SSTRIDE
    float* asv = smem + 2 * 128 * SSTRIDE;   // 128
    float* adv = asv + 128;                  // 128
    int node0 = blockIdx.x * 128;
    int tid = threadIdx.x;

    if (tid < 128) asv[tid] = a_s[tid];
    else adv[tid - 128] = a_d[tid - 128];

    for (int i = tid; i < 128 * 32; i += 256) {
        int r = i >> 5, c4 = i & 31;
        int row = node0 + r;
        float4 v = make_float4(0.f, 0.f, 0.f, 0.f);
        if (row < N_NODES) v = reinterpret_cast<const float4*>(x + (size_t)row * FIN)[c4];
        uint32_t u0, u1, u2, u3;
        asm("cvt.rna.tf32.f32 %0, %1;" : "=r"(u0) : "f"(v.x));
        asm("cvt.rna.tf32.f32 %0, %1;" : "=r"(u1) : "f"(v.y));
        asm("cvt.rna.tf32.f32 %0, %1;" : "=r"(u2) : "f"(v.z));
        asm("cvt.rna.tf32.f32 %0, %1;" : "=r"(u3) : "f"(v.w));
        *reinterpret_cast<uint4*>(&As[r * SSTRIDE + c4 * 4]) = make_uint4(u0, u1, u2, u3);
    }
    for (int i = tid; i < 128 * 32; i += 256) {
        int k = i >> 5, c4 = i & 31;
        float4 v = reinterpret_cast<const float4*>(W + k * HF)[c4];
        uint32_t u0, u1, u2, u3;
        asm("cvt.rna.tf32.f32 %0, %1;" : "=r"(u0) : "f"(v.x));
        asm("cvt.rna.tf32.f32 %0, %1;" : "=r"(u1) : "f"(v.y));
        asm("cvt.rna.tf32.f32 %0, %1;" : "=r"(u2) : "f"(v.z));
        asm("cvt.rna.tf32.f32 %0, %1;" : "=r"(u3) : "f"(v.w));
        *reinterpret_cast<uint4*>(&Ws[k * SSTRIDE + c4 * 4]) = make_uint4(u0, u1, u2, u3);
    }
    __syncthreads();

    int warp = tid >> 5, lane = tid & 31;
    int qr = lane >> 2, qc = lane & 3;
    int arow = warp * 16 + qr;

    float c[16][4];
#pragma unroll
    for (int t = 0; t < 16; t++) { c[t][0] = c[t][1] = c[t][2] = c[t][3] = 0.f; }

    const uint32_t* Asu = reinterpret_cast<const uint32_t*>(As);
    const uint32_t* Wsu = reinterpret_cast<const uint32_t*>(Ws);

#pragma unroll
    for (int ks = 0; ks < 16; ks++) {
        int k0 = ks * 8;
        uint32_t a0 = Asu[arow * SSTRIDE + k0 + qc];
        uint32_t a1 = Asu[(arow + 8) * SSTRIDE + k0 + qc];
        uint32_t a2 = Asu[arow * SSTRIDE + k0 + 4 + qc];
        uint32_t a3 = Asu[(arow + 8) * SSTRIDE + k0 + 4 + qc];
#pragma unroll
        for (int nt = 0; nt < 16; nt++) {
            uint32_t b0 = Wsu[(k0 + qc) * SSTRIDE + nt * 8 + qr];
            uint32_t b1 = Wsu[(k0 + 4 + qc) * SSTRIDE + nt * 8 + qr];
            asm("mma.sync.aligned.m16n8k8.row.col.f32.tf32.tf32.f32 "
                "{%0,%1,%2,%3}, {%4,%5,%6,%7}, {%8,%9}, {%0,%1,%2,%3};"
                : "+f"(c[nt][0]), "+f"(c[nt][1]), "+f"(c[nt][2]), "+f"(c[nt][3])
                : "r"(a0), "r"(a1), "r"(a2), "r"(a3), "r"(b0), "r"(b1));
        }
    }

    int r0 = node0 + arow;
    int r1 = r0 + 8;
    bool l0 = (r0 < N_NODES), l1 = (r1 < N_NODES);

    // h1 fp16 store
#pragma unroll
    for (int nt = 0; nt < 16; nt++) {
        int col = nt * 8 + qc * 2;
        if (l0) *reinterpret_cast<__half2*>(&g_h1h[(size_t)r0 * HF + col]) =
            __floats2half2_rn(c[nt][0], c[nt][1]);
        if (l1) *reinterpret_cast<__half2*>(&g_h1h[(size_t)r1 * HF + col]) =
            __floats2half2_rn(c[nt][2], c[nt][3]);
    }

    // fused alpha1: per head h, cols nt in {2h, 2h+1}
#pragma unroll
    for (int h = 0; h < NHEAD; h++) {
        int cA = h * 16 + qc * 2;
        int cB = h * 16 + 8 + qc * 2;
        float sA0 = asv[cA], sA1 = asv[cA + 1], sB0 = asv[cB], sB1 = asv[cB + 1];
        float dA0 = adv[cA], dA1 = adv[cA + 1], dB0 = adv[cB], dB1 = adv[cB + 1];
        float ps0 = c[2*h][0]*sA0 + c[2*h][1]*sA1 + c[2*h+1][0]*sB0 + c[2*h+1][1]*sB1;
        float ps1 = c[2*h][2]*sA0 + c[2*h][3]*sA1 + c[2*h+1][2]*sB0 + c[2*h+1][3]*sB1;
        float pd0 = c[2*h][0]*dA0 + c[2*h][1]*dA1 + c[2*h+1][0]*dB0 + c[2*h+1][1]*dB1;
        float pd1 = c[2*h][2]*dA0 + c[2*h][3]*dA1 + c[2*h+1][2]*dB0 + c[2*h+1][3]*dB1;
        ps0 += __shfl_xor_sync(0xffffffffu, ps0, 1);
        ps0 += __shfl_xor_sync(0xffffffffu, ps0, 2);
        ps1 += __shfl_xor_sync(0xffffffffu, ps1, 1);
        ps1 += __shfl_xor_sync(0xffffffffu, ps1, 2);
        pd0 += __shfl_xor_sync(0xffffffffu, pd0, 1);
        pd0 += __shfl_xor_sync(0xffffffffu, pd0, 2);
        pd1 += __shfl_xor_sync(0xffffffffu, pd1, 1);
        pd1 += __shfl_xor_sync(0xffffffffu, pd1, 2);
        if (qc == 0) {
            if (l0) { g_as1[r0 * NHEAD + h] = ps0; g_ad1[r0 * NHEAD + h] = pd0; }
            if (l1) { g_as1[r1 * NHEAD + h] = ps1; g_ad1[r1 * NHEAD + h] = pd1; }
        }
    }
}

// ---------------- Aggregation layer 1 (fp16 gather, fused bias+ELU) ----------------
__global__ void agg1_kernel(const float* __restrict__ b1) {
    int warp = threadIdx.x >> 5, lane = threadIdx.x & 31;
    int n = blockIdx.x * 8 + warp;
    if (n >= N_NODES) return;
    int h = lane >> 2;
    float ad = __ldg(&g_ad1[n * NHEAD + h]);
    int beg = __ldg(&g_rowptr[n]), end = __ldg(&g_rowptr[n + 1]);
    float4 acc = make_float4(0.f, 0.f, 0.f, 0.f);
    float denom = 0.f;
    int s_next = (beg < end) ? __ldg(&g_csr[beg]) : 0;
#pragma unroll 2
    for (int i = beg; i < end; i++) {
        int s = s_next;
        if (i + 1 < end) s_next = __ldg(&g_csr[i + 1]);
        float e = __ldg(&g_as1[s * NHEAD + h]) + ad;
        e = fmaxf(e, NEG * e);
        float w = __expf(e);
        denom += w;
        const __half2* hp = reinterpret_cast<const __half2*>(&g_h1h[(size_t)s * HF + lane * 4]);
        float2 f0 = __half22float2(hp[0]);
        float2 f1 = __half22float2(hp[1]);
        acc.x += w * f0.x; acc.y += w * f0.y;
        acc.z += w * f1.x; acc.w += w * f1.y;
    }
    float r = 1.0f / fmaxf(denom, 1e-16f);
    float4 bv = __ldg(&reinterpret_cast<const float4*>(b1)[lane]);
    float4 o;
    o.x = acc.x * r + bv.x; o.y = acc.y * r + bv.y;
    o.z = acc.z * r + bv.z; o.w = acc.w * r + bv.w;
    o.x = o.x > 0.f ? o.x : __expf(o.x) - 1.f;
    o.y = o.y > 0.f ? o.y : __expf(o.y) - 1.f;
    o.z = o.z > 0.f ? o.z : __expf(o.z) - 1.f;
    o.w = o.w > 0.f ? o.w : __expf(o.w) - 1.f;
    *reinterpret_cast<float4*>(&g_h2[(size_t)n * HF + lane * 4]) = o;
}

// ---------------- GEMM2 (tf32 mma): hp2 = h2 @ W2, fused alpha2 ----------------
#define W2S 40
__global__ __launch_bounds__(256) void gemm2_tf32_kernel(
        const float* __restrict__ W2,
        const float* __restrict__ a_s, const float* __restrict__ a_d) {
    extern __shared__ float smem[];
    float* As = smem;                        // 128 x SSTRIDE
    float* Ws = smem + 128 * SSTRIDE;        // 128 x 40
    float* asv = Ws + 128 * W2S;             // 40
    float* adv = asv + 64;                   // 40
    int node0 = blockIdx.x * 128;
    int tid = threadIdx.x;

    if (tid < C2) asv[tid] = a_s[tid];
    else if (tid >= 64 && tid < 64 + C2) adv[tid - 64] = a_d[tid - 64];

    for (int i = tid; i < 128 * W2S; i += 256) {
        uint32_t u;
        asm("cvt.rna.tf32.f32 %0, %1;" : "=r"(u) : "f"(W2[i]));
        reinterpret_cast<uint32_t*>(Ws)[i] = u;
    }
    for (int i = tid; i < 128 * 32; i += 256) {
        int r = i >> 5, c4 = i & 31;
        int row = node0 + r;
        float4 v = make_float4(0.f, 0.f, 0.f, 0.f);
        if (row < N_NODES) v = reinterpret_cast<const float4*>(g_h2 + (size_t)row * FIN)[c4];
        uint32_t u0, u1, u2, u3;
        asm("cvt.rna.tf32.f32 %0, %1;" : "=r"(u0) : "f"(v.x));
        asm("cvt.rna.tf32.f32 %0, %1;" : "=r"(u1) : "f"(v.y));
        asm("cvt.rna.tf32.f32 %0, %1;" : "=r"(u2) : "f"(v.z));
        asm("cvt.rna.tf32.f32 %0, %1;" : "=r"(u3) : "f"(v.w));
        *reinterpret_cast<uint4*>(&As[r * SSTRIDE + c4 * 4]) = make_uint4(u0, u1, u2, u3);
    }
    __syncthreads();

    int warp = tid >> 5, lane = tid & 31;
    int qr = lane >> 2, qc = lane & 3;
    int arow = warp * 16 + qr;

    float c[5][4];
#pragma unroll
    for (int t = 0; t < 5; t++) { c[t][0] = c[t][1] = c[t][2] = c[t][3] = 0.f; }

    const uint32_t* Asu = reinterpret_cast<const uint32_t*>(As);
    const uint32_t* Wsu = reinterpret_cast<const uint32_t*>(Ws);

#pragma unroll
    for (int ks = 0; ks < 16; ks++) {
        int k0 = ks * 8;
        uint32_t a0 = Asu[arow * SSTRIDE + k0 + qc];
        uint32_t a1 = Asu[(arow + 8) * SSTRIDE + k0 + qc];
        uint32_t a2 = Asu[arow * SSTRIDE + k0 + 4 + qc];
        uint32_t a3 = Asu[(arow + 8) * SSTRIDE + k0 + 4 + qc];
#pragma unroll
        for (int nt = 0; nt < 5; nt++) {
            uint32_t b0 = Wsu[(k0 + qc) * W2S + nt * 8 + qr];
            uint32_t b1 = Wsu[(k0 + 4 + qc) * W2S + nt * 8 + qr];
            asm("mma.sync.aligned.m16n8k8.row.col.f32.tf32.tf32.f32 "
                "{%0,%1,%2,%3}, {%4,%5,%6,%7}, {%8,%9}, {%0,%1,%2,%3};"
                : "+f"(c[nt][0]), "+f"(c[nt][1]), "+f"(c[nt][2]), "+f"(c[nt][3])
                : "r"(a0), "r"(a1), "r"(a2), "r"(a3), "r"(b0), "r"(b1));
        }
    }

    int r0 = node0 + arow;
    int r1 = r0 + 8;
    bool l0 = (r0 < N_NODES), l1 = (r1 < N_NODES);

    float ps0 = 0.f, ps1 = 0.f, pd0 = 0.f, pd1 = 0.f;
#pragma unroll
    for (int nt = 0; nt < 5; nt++) {
        int col = nt * 8 + qc * 2;
        if (l0) *reinterpret_cast<float2*>(&g_hp2[(size_t)r0 * HP2S + col]) =
            make_float2(c[nt][0], c[nt][1]);
        if (l1) *reinterpret_cast<float2*>(&g_hp2[(size_t)r1 * HP2S + col]) =
            make_float2(c[nt][2], c[nt][3]);
        float s0 = asv[col], s1 = asv[col + 1], d0 = adv[col], d1 = adv[col + 1];
        ps0 += c[nt][0] * s0 + c[nt][1] * s1;
        ps1 += c[nt][2] * s0 + c[nt][3] * s1;
        pd0 += c[nt][0] * d0 + c[nt][1] * d1;
        pd1 += c[nt][2] * d0 + c[nt][3] * d1;
    }
    ps0 += __shfl_xor_sync(0xffffffffu, ps0, 1);
    ps0 += __shfl_xor_sync(0xffffffffu, ps0, 2);
    ps1 += __shfl_xor_sync(0xffffffffu, ps1, 1);
    ps1 += __shfl_xor_sync(0xffffffffu, ps1, 2);
    pd0 += __shfl_xor_sync(0xffffffffu, pd0, 1);
    pd0 += __shfl_xor_sync(0xffffffffu, pd0, 2);
    pd1 += __shfl_xor_sync(0xffffffffu, pd1, 1);
    pd1 += __shfl_xor_sync(0xffffffffu, pd1, 2);
    if (qc == 0) {
        if (l0) { g_as2[r0] = ps0; g_ad2[r0] = pd0; }
        if (l1) { g_as2[r1] = ps1; g_ad2[r1] = pd1; }
    }
}

// ---------------- Aggregation layer 2 ----------------
__global__ void agg2_kernel(const float* __restrict__ b2, float* __restrict__ out) {
    int warp = threadIdx.x >> 5, lane = threadIdx.x & 31;
    int n = blockIdx.x * 8 + warp;
    if (n >= N_NODES) return;
    float ad = __ldg(&g_ad2[n]);
    int beg = __ldg(&g_rowptr[n]), end = __ldg(&g_rowptr[n + 1]);
    float acc0 = 0.f, acc1 = 0.f, denom = 0.f;
    int s_next = (beg < end) ? __ldg(&g_csr[beg]) : 0;
#pragma unroll 2
    for (int i = beg; i < end; i++) {
        int s = s_next;
        if (i + 1 < end) s_next = __ldg(&g_csr[i + 1]);
        float e = __ldg(&g_as2[s]) + ad;
        e = fmaxf(e, NEG * e);
        float w = __expf(e);
        denom += w;
        acc0 += w * __ldg(&g_hp2[(size_t)s * HP2S + lane]);
        if (lane < 8) acc1 += w * __ldg(&g_hp2[(size_t)s * HP2S + 32 + lane]);
    }
    float r = 1.0f / fmaxf(denom, 1e-16f);
    out[(size_t)n * C2 + lane] = acc0 * r + __ldg(&b2[lane]);
    if (lane < 8) out[(size_t)n * C2 + 32 + lane] = acc1 * r + __ldg(&b2[32 + lane]);
}

// ---------------- launch ----------------
extern "C" void kernel_launch(void* const* d_in, const int* in_sizes, int n_in,
                              void* d_out, int out_size) {
    const float* x    = (const float*)d_in[0];
    const int*   esrc = (const int*)d_in[1];
    const int*   edst = (const int*)d_in[2];
    const float* W1   = (const float*)d_in[3];
    const float* as1  = (const float*)d_in[4];
    const float* ad1  = (const float*)d_in[5];
    const float* b1   = (const float*)d_in[6];
    const float* W2   = (const float*)d_in[7];
    const float* as2  = (const float*)d_in[8];
    const float* ad2  = (const float*)d_in[9];
    const float* b2   = (const float*)d_in[10];
    float*       out  = (float*)d_out;

    static cudaStream_t s2 = nullptr;
    static cudaEvent_t evFork = nullptr, evJoin = nullptr;
    static int smem1 = 0, smem2 = 0;
    if (!s2) {
        cudaStreamCreate(&s2);
        cudaEventCreateWithFlags(&evFork, cudaEventDisableTiming);
        cudaEventCreateWithFlags(&evJoin, cudaEventDisableTiming);
        smem1 = (2 * 128 * SSTRIDE + 256) * (int)sizeof(float);
        smem2 = (128 * SSTRIDE + 128 * W2S + 128) * (int)sizeof(float);
        cudaFuncSetAttribute(gemm1_tf32_kernel, cudaFuncAttributeMaxDynamicSharedMemorySize, smem1);
        cudaFuncSetAttribute(gemm2_tf32_kernel, cudaFuncAttributeMaxDynamicSharedMemorySize, smem2);
    }

    void* degptr = nullptr;
    cudaGetSymbolAddress(&degptr, g_deg);

    // fork: CSR build on s2, gemm1 on capture stream
    cudaEventRecord(evFork, 0);
    cudaStreamWaitEvent(s2, evFork, 0);
    cudaMemsetAsync(degptr, 0, N_NODES * sizeof(int), s2);
    count_deg_kernel<<<(N_EDGES + 255) / 256, 256, 0, s2>>>(edst);
    scan_a_kernel<<<SCAN_NBLK, 1024, 0, s2>>>();
    scan_b_kernel<<<1, 128, 0, s2>>>();
    scan_c_kernel<<<(N_NODES + 255) / 256, 256, 0, s2>>>();
    scatter_kernel<<<(N_EDGES + 255) / 256, 256, 0, s2>>>(esrc, edst);
    cudaEventRecord(evJoin, s2);

    gemm1_tf32_kernel<<<(N_NODES + 127) / 128, 256, smem1>>>(x, W1, as1, ad1);

    cudaStreamWaitEvent(0, evJoin, 0);
    agg1_kernel<<<(N_NODES + 7) / 8, 256>>>(b1);
    gemm2_tf32_kernel<<<(N_NODES + 127) / 128, 256, smem2>>>(W2, as2, ad2);
    agg2_kernel<<<(N_NODES + 7) / 8, 256>>>(b2, out);
}